// round 1
// baseline (speedup 1.0000x reference)
#include <cuda_runtime.h>
#include <cuda_bf16.h>
#include <math.h>

// ---------------- scratch (no allocation allowed) ----------------
#define BATCH 32
__device__ float g_A[BATCH*64*64*64];    // conv1 out / dt1 out (33.5MB)
__device__ float g_B[BATCH*128*32*32];   // conv2 out / decoder g
__device__ float g_C[BATCH*128*32*32];   // encoder h
__device__ float g_R[BATCH*32*32*32];    // residual branch temp
__device__ float g_Z[BATCH*64*32*32];    // pre-VQ z
__device__ float g_Q[BATCH*64*32*32];    // quantized (NCHW)
__device__ int   g_hist[512];
__device__ float g_ssep[128];            // per-block SSE partials (deterministic)

// ---------------- zero histogram ----------------
__global__ void zero_kernel(int* hist) {
    int t = blockIdx.x * blockDim.x + threadIdx.x;
    if (t < 512) hist[t] = 0;
}

// ---------------- conv k=4 s=2 p=1, bias, optional out-relu ----------------
// block: 256 thr -> 16x16 output tile, 8 out channels. grid(tiles, Cout/8, B)
__global__ void conv_k4s2_kernel(const float* __restrict__ in, const float* __restrict__ w,
                                 const float* __restrict__ bias, float* __restrict__ out,
                                 int Cin, int Hin, int Win, int Cout, int Hout, int Wout,
                                 int outRelu)
{
    __shared__ float s_in[8][34][36];
    __shared__ float s_w[8][8][16];
    int tid = threadIdx.x;
    int ntx = Wout >> 4;
    int tx0 = (blockIdx.x % ntx) << 4, ty0 = (blockIdx.x / ntx) << 4;
    int ocb = blockIdx.y << 3;
    int b = blockIdx.z;
    int px = tid & 15, py = tid >> 4;
    float acc[8];
#pragma unroll
    for (int i = 0; i < 8; i++) acc[i] = 0.f;

    for (int c0 = 0; c0 < Cin; c0 += 8) {
        int cc = min(8, Cin - c0);
        for (int i = tid; i < cc * 34 * 34; i += 256) {
            int ci = i / (34*34); int rr = (i / 34) % 34; int col = i % 34;
            int gy = 2*ty0 - 1 + rr, gx = 2*tx0 - 1 + col;
            float v = 0.f;
            if ((unsigned)gy < (unsigned)Hin && (unsigned)gx < (unsigned)Win)
                v = in[((b*Cin + c0 + ci)*Hin + gy)*Win + gx];
            s_in[ci][rr][col] = v;
        }
        for (int i = tid; i < 8 * cc * 16; i += 256) {
            int oc = i / (cc*16); int ci = (i / 16) % cc; int k = i & 15;
            s_w[oc][ci][k] = w[((ocb+oc)*Cin + c0 + ci)*16 + k];
        }
        __syncthreads();
        for (int ci = 0; ci < cc; ci++) {
            float v[16];
#pragma unroll
            for (int ky = 0; ky < 4; ky++)
#pragma unroll
                for (int kx = 0; kx < 4; kx++)
                    v[ky*4+kx] = s_in[ci][2*py + ky][2*px + kx];
#pragma unroll
            for (int oc = 0; oc < 8; oc++) {
                float a = acc[oc];
#pragma unroll
                for (int k = 0; k < 16; k++) a += v[k] * s_w[oc][ci][k];
                acc[oc] = a;
            }
        }
        __syncthreads();
    }
#pragma unroll
    for (int oc = 0; oc < 8; oc++) {
        float r = acc[oc] + bias[ocb + oc];
        if (outRelu) r = fmaxf(r, 0.f);
        out[((b*Cout + ocb + oc)*Hout + ty0 + py)*Wout + tx0 + px] = r;
    }
}

// ---------------- conv k=3 s=1 p=1, optional in-relu, optional bias ----------------
// block: 256 thr -> 16x16 tile, 8 oc. grid(tiles, Cout/8, B). Cin % 8 == 0.
__global__ void conv3x3_kernel(const float* __restrict__ in, const float* __restrict__ w,
                               const float* __restrict__ bias, float* __restrict__ out,
                               int Cin, int Cout, int H, int W, int inRelu)
{
    __shared__ float s_in[8][18][20];
    __shared__ float s_w[8][8][9];
    int tid = threadIdx.x;
    int ntx = W >> 4;
    int tx0 = (blockIdx.x % ntx) << 4, ty0 = (blockIdx.x / ntx) << 4;
    int ocb = blockIdx.y << 3;
    int b = blockIdx.z;
    int px = tid & 15, py = tid >> 4;
    float acc[8];
#pragma unroll
    for (int i = 0; i < 8; i++) acc[i] = 0.f;

    for (int c0 = 0; c0 < Cin; c0 += 8) {
        for (int i = tid; i < 8 * 18 * 18; i += 256) {
            int ci = i / 324; int rr = (i / 18) % 18; int col = i % 18;
            int gy = ty0 - 1 + rr, gx = tx0 - 1 + col;
            float v = 0.f;
            if ((unsigned)gy < (unsigned)H && (unsigned)gx < (unsigned)W)
                v = in[((b*Cin + c0 + ci)*H + gy)*W + gx];
            if (inRelu) v = fmaxf(v, 0.f);
            s_in[ci][rr][col] = v;
        }
        for (int i = tid; i < 8 * 8 * 9; i += 256) {
            int oc = i / 72; int rem = i % 72; int ci = rem / 9; int k = rem % 9;
            s_w[oc][ci][k] = w[((ocb+oc)*Cin + c0 + ci)*9 + k];
        }
        __syncthreads();
#pragma unroll
        for (int ci = 0; ci < 8; ci++) {
            float v[9];
#pragma unroll
            for (int ky = 0; ky < 3; ky++)
#pragma unroll
                for (int kx = 0; kx < 3; kx++)
                    v[ky*3+kx] = s_in[ci][py + ky][px + kx];
#pragma unroll
            for (int oc = 0; oc < 8; oc++) {
                float a = acc[oc];
#pragma unroll
                for (int k = 0; k < 9; k++) a += v[k] * s_w[oc][ci][k];
                acc[oc] = a;
            }
        }
        __syncthreads();
    }
#pragma unroll
    for (int oc = 0; oc < 8; oc++) {
        float r = acc[oc] + (bias ? bias[ocb + oc] : 0.f);
        out[((b*Cout + ocb + oc)*H + ty0 + py)*W + tx0 + px] = r;
    }
}

// ---------------- conv 1x1 (in-relu) + optional bias + optional residual add ----------------
// grid(HW/256, Cout, B)
__global__ void conv1x1_kernel(const float* __restrict__ in, const float* __restrict__ w,
                               const float* __restrict__ bias, const float* __restrict__ hres,
                               float* __restrict__ out, int Cin, int Cout, int HW)
{
    int s = blockIdx.x * 256 + threadIdx.x;
    int oc = blockIdx.y;
    int b = blockIdx.z;
    const float* ip = in + (size_t)b * Cin * HW + s;
    const float* wp = w + (size_t)oc * Cin;
    float acc = 0.f;
    for (int ci = 0; ci < Cin; ci++)
        acc += fmaxf(ip[(size_t)ci * HW], 0.f) * wp[ci];
    size_t oidx = ((size_t)b * Cout + oc) * HW + s;
    if (hres) acc += hres[oidx];
    if (bias) acc += bias[oc];
    out[oidx] = acc;
}

// ---------------- vector quantizer ----------------
// grid(128), 256 thr; one thread per (b, spatial). z: [B,64,32,32]
__global__ void vq_kernel(const float* __restrict__ z, const float* __restrict__ cb,
                          float* __restrict__ qc, int* __restrict__ hist,
                          float* __restrict__ ssep)
{
    __shared__ float s_cb[128][64];
    __shared__ float s_cn[128];
    __shared__ int s_hist[512];
    __shared__ float s_red[256];
    int tid = threadIdx.x;
    for (int i = tid; i < 512; i += 256) s_hist[i] = 0;

    int n = blockIdx.x * 256 + tid;
    int b = n >> 10, s = n & 1023;
    float zv[64];
#pragma unroll
    for (int d = 0; d < 64; d++) zv[d] = z[(((size_t)b * 64 + d) << 10) + s];

    float best = 3.4e38f; int bi = 0;
    for (int k0 = 0; k0 < 512; k0 += 128) {
        __syncthreads();
        for (int i = tid; i < 128 * 64; i += 256)
            s_cb[i >> 6][i & 63] = cb[((size_t)k0 << 6) + i];
        __syncthreads();
        if (tid < 128) {
            float cn = 0.f;
#pragma unroll
            for (int d = 0; d < 64; d++) { float c = s_cb[tid][d]; cn += c * c; }
            s_cn[tid] = cn;
        }
        __syncthreads();
        for (int k = 0; k < 128; k++) {
            float dot = 0.f;
#pragma unroll
            for (int d = 0; d < 64; d++) dot += zv[d] * s_cb[k][d];
            float dd = s_cn[k] - 2.f * dot;
            if (dd < best) { best = dd; bi = k0 + k; }
        }
    }
    // write quantized output + squared error
    float sq = 0.f;
    const float* c = cb + ((size_t)bi << 6);
#pragma unroll
    for (int d = 0; d < 64; d++) {
        float cv = c[d];
        qc[(((size_t)b * 64 + d) << 10) + s] = cv;
        float df = cv - zv[d];
        sq += df * df;
    }
    atomicAdd(&s_hist[bi], 1);
    s_red[tid] = sq;
    __syncthreads();
    for (int st = 128; st > 0; st >>= 1) {
        if (tid < st) s_red[tid] += s_red[tid + st];
        __syncthreads();
    }
    if (tid == 0) ssep[blockIdx.x] = s_red[0];
    for (int i = tid; i < 512; i += 256)
        if (s_hist[i]) atomicAdd(&hist[i], s_hist[i]);
}

// ---------------- conv transpose k=4 s=2 p=1 ----------------
// block: 256 thr -> 16x16 OUTPUT tile, 8 oc. grid(tiles, ceil(Cout/8), B)
__global__ void convt4s2_kernel(const float* __restrict__ in, const float* __restrict__ w,
                                const float* __restrict__ bias, float* __restrict__ out,
                                int Cin, int Hin, int Win, int Cout, int inRelu, int outRelu)
{
    __shared__ float s_in[8][10][12];
    __shared__ float s_w[8][8][16];
    int tid = threadIdx.x;
    int Hout = Hin * 2, Wout = Win * 2;
    int ntx = Wout >> 4;
    int ox0 = (blockIdx.x % ntx) << 4, oy0 = (blockIdx.x / ntx) << 4;
    int ocb = blockIdx.y << 3;
    int b = blockIdx.z;
    int px = tid & 15, py = tid >> 4;
    int iy0 = oy0 >> 1, ix0 = ox0 >> 1;
    float acc[8];
#pragma unroll
    for (int i = 0; i < 8; i++) acc[i] = 0.f;

    for (int c0 = 0; c0 < Cin; c0 += 8) {
        for (int i = tid; i < 8 * 10 * 10; i += 256) {
            int ci = i / 100; int rr = (i / 10) % 10; int col = i % 10;
            int gy = iy0 - 1 + rr, gx = ix0 - 1 + col;
            float v = 0.f;
            if ((unsigned)gy < (unsigned)Hin && (unsigned)gx < (unsigned)Win)
                v = in[((b*Cin + c0 + ci)*Hin + gy)*Win + gx];
            if (inRelu) v = fmaxf(v, 0.f);
            s_in[ci][rr][col] = v;
        }
        for (int i = tid; i < 8 * 8 * 16; i += 256) {
            int oc = i >> 7; int ci = (i >> 4) & 7; int k = i & 15;
            int oco = ocb + oc;
            s_w[oc][ci][k] = (oco < Cout) ? w[((size_t)oco * Cin + c0 + ci)*16 + k] : 0.f;
        }
        __syncthreads();
        int ky0 = py & 1, kx0 = px & 1;
        int r0 = (py + ky0) >> 1;
        int q0 = (px + kx0) >> 1;
#pragma unroll
        for (int ci = 0; ci < 8; ci++) {
            float v00 = s_in[ci][r0][q0];
            float v01 = s_in[ci][r0][q0 + 1];
            float v10 = s_in[ci][r0 + 1][q0];
            float v11 = s_in[ci][r0 + 1][q0 + 1];
#pragma unroll
            for (int oc = 0; oc < 8; oc++) {
                float a = acc[oc];
                a += v00 * s_w[oc][ci][ky0*4 + kx0];
                a += v01 * s_w[oc][ci][ky0*4 + kx0 + 2];
                a += v10 * s_w[oc][ci][(ky0+2)*4 + kx0];
                a += v11 * s_w[oc][ci][(ky0+2)*4 + kx0 + 2];
                acc[oc] = a;
            }
        }
        __syncthreads();
    }
#pragma unroll
    for (int oc = 0; oc < 8; oc++) {
        int oco = ocb + oc;
        if (oco < Cout) {
            float r = acc[oc] + bias[oco];
            if (outRelu) r = fmaxf(r, 0.f);
            out[(((size_t)b * Cout + oco)*Hout + oy0 + py)*Wout + ox0 + px] = r;
        }
    }
}

// ---------------- loss + perplexity finalize ----------------
__global__ void finalize_kernel(const int* __restrict__ hist, const float* __restrict__ ssep,
                                float* __restrict__ out, int lastIdx)
{
    __shared__ float red[512];
    __shared__ float red2[128];
    int t = threadIdx.x;
    float p = hist[t] * (1.0f / 32768.0f);
    red[t] = p * logf(p + 1e-10f);
    if (t < 128) red2[t] = ssep[t];
    __syncthreads();
    for (int st = 256; st > 0; st >>= 1) {
        if (t < st) red[t] += red[t + st];
        __syncthreads();
    }
    for (int st = 64; st > 0; st >>= 1) {
        if (t < st) red2[t] += red2[t + st];
        __syncthreads();
    }
    if (t == 0) {
        out[0] = red2[0] * 1.25f / (32768.0f * 64.0f);   // q_latent + beta*e_latent
        out[lastIdx] = expf(-red[0]);                     // perplexity
    }
}

// ---------------- launch ----------------
extern "C" void kernel_launch(void* const* d_in, const int* in_sizes, int n_in,
                              void* d_out, int out_size)
{
    const float* x     = (const float*)d_in[0];
    const float* e_w1  = (const float*)d_in[1];
    const float* e_b1  = (const float*)d_in[2];
    const float* e_w2  = (const float*)d_in[3];
    const float* e_b2  = (const float*)d_in[4];
    const float* e_w3  = (const float*)d_in[5];
    const float* e_b3  = (const float*)d_in[6];
    const float* e_r1a = (const float*)d_in[7];
    const float* e_r1b = (const float*)d_in[8];
    const float* e_r2a = (const float*)d_in[9];
    const float* e_r2b = (const float*)d_in[10];
    const float* pre_w = (const float*)d_in[11];
    const float* pre_b = (const float*)d_in[12];
    const float* cb    = (const float*)d_in[13];
    const float* d_w1  = (const float*)d_in[14];
    const float* d_b1  = (const float*)d_in[15];
    const float* d_r1a = (const float*)d_in[16];
    const float* d_r1b = (const float*)d_in[17];
    const float* d_r2a = (const float*)d_in[18];
    const float* d_r2b = (const float*)d_in[19];
    const float* dt_w1 = (const float*)d_in[20];
    const float* dt_b1 = (const float*)d_in[21];
    const float* dt_w2 = (const float*)d_in[22];
    const float* dt_b2 = (const float*)d_in[23];
    float* out = (float*)d_out;

    float *A, *Bb, *C, *R, *Z, *Q, *ssep; int* hist;
    cudaGetSymbolAddress((void**)&A,    g_A);
    cudaGetSymbolAddress((void**)&Bb,   g_B);
    cudaGetSymbolAddress((void**)&C,    g_C);
    cudaGetSymbolAddress((void**)&R,    g_R);
    cudaGetSymbolAddress((void**)&Z,    g_Z);
    cudaGetSymbolAddress((void**)&Q,    g_Q);
    cudaGetSymbolAddress((void**)&ssep, g_ssep);
    cudaGetSymbolAddress((void**)&hist, g_hist);

    zero_kernel<<<2, 256>>>(hist);

    // ---- encoder ----
    // conv1: 3->64, 128->64, k4s2p1, relu
    conv_k4s2_kernel<<<dim3(16, 8, BATCH), 256>>>(x, e_w1, e_b1, A, 3, 128, 128, 64, 64, 64, 1);
    // conv2: 64->128, 64->32, relu
    conv_k4s2_kernel<<<dim3(4, 16, BATCH), 256>>>(A, e_w2, e_b2, Bb, 64, 64, 64, 128, 32, 32, 1);
    // conv3: 128->128, 3x3 p1, bias, no relu
    conv3x3_kernel<<<dim3(4, 16, BATCH), 256>>>(Bb, e_w3, e_b3, C, 128, 128, 32, 32, 0);
    // res block 1
    conv3x3_kernel<<<dim3(4, 4, BATCH), 256>>>(C, e_r1a, nullptr, R, 128, 32, 32, 32, 1);
    conv1x1_kernel<<<dim3(4, 128, BATCH), 256>>>(R, e_r1b, nullptr, C, C, 32, 128, 1024);
    // res block 2
    conv3x3_kernel<<<dim3(4, 4, BATCH), 256>>>(C, e_r2a, nullptr, R, 128, 32, 32, 32, 1);
    conv1x1_kernel<<<dim3(4, 128, BATCH), 256>>>(R, e_r2b, nullptr, C, C, 32, 128, 1024);
    // pre-VQ 1x1 (in-relu applies the res-stack's final relu): 128->64, bias
    conv1x1_kernel<<<dim3(4, 64, BATCH), 256>>>(C, pre_w, pre_b, nullptr, Z, 128, 64, 1024);

    // ---- vector quantizer ----
    vq_kernel<<<128, 256>>>(Z, cb, Q, hist, ssep);

    // ---- decoder ----
    conv3x3_kernel<<<dim3(4, 16, BATCH), 256>>>(Q, d_w1, d_b1, Bb, 64, 128, 32, 32, 0);
    conv3x3_kernel<<<dim3(4, 4, BATCH), 256>>>(Bb, d_r1a, nullptr, R, 128, 32, 32, 32, 1);
    conv1x1_kernel<<<dim3(4, 128, BATCH), 256>>>(R, d_r1b, nullptr, Bb, Bb, 32, 128, 1024);
    conv3x3_kernel<<<dim3(4, 4, BATCH), 256>>>(Bb, d_r2a, nullptr, R, 128, 32, 32, 32, 1);
    conv1x1_kernel<<<dim3(4, 128, BATCH), 256>>>(R, d_r2b, nullptr, Bb, Bb, 32, 128, 1024);
    // dt1: 128->64, 32->64, in-relu (res stack final relu) + out-relu
    convt4s2_kernel<<<dim3(16, 8, BATCH), 256>>>(Bb, dt_w1, dt_b1, A, 128, 32, 32, 64, 1, 1);
    // dt2: 64->3, 64->128, writes x_recon at out+1
    convt4s2_kernel<<<dim3(64, 1, BATCH), 256>>>(A, dt_w2, dt_b2, out + 1, 64, 64, 64, 3, 0, 0);

    // ---- scalars ----
    finalize_kernel<<<1, 512>>>(hist, ssep, out, out_size - 1);
}

// round 3
// speedup vs baseline: 1.5252x; 1.5252x over previous
#include <cuda_runtime.h>
#include <cuda_bf16.h>
#include <math.h>

typedef unsigned long long ull;

// ---------------- packed f32x2 helpers ----------------
__device__ __forceinline__ ull pack2(float lo, float hi) {
    ull r; asm("mov.b64 %0, {%1, %2};" : "=l"(r) : "f"(lo), "f"(hi)); return r;
}
__device__ __forceinline__ ull bc2(float v) { return pack2(v, v); }
__device__ __forceinline__ void ffma2(ull& d, ull a, ull b) {
    asm("fma.rn.f32x2 %0, %1, %2, %0;" : "+l"(d) : "l"(a), "l"(b));
}
__device__ __forceinline__ float lo32(ull v) { return __uint_as_float((unsigned)v); }
__device__ __forceinline__ float hi32(ull v) { return __uint_as_float((unsigned)(v >> 32)); }

// ---------------- scratch ----------------
#define BATCH 32
__device__ float g_A[BATCH*64*64*64];
__device__ float g_B[BATCH*128*32*32];
__device__ float g_C[BATCH*128*32*32];
__device__ float g_R[BATCH*32*32*32];
__device__ float g_Z[BATCH*64*32*32];
__device__ float g_Q[BATCH*64*32*32];
__device__ int   g_hist[512];
__device__ float g_ssep[128];

__global__ void zero_kernel(int* hist) {
    int t = blockIdx.x * blockDim.x + threadIdx.x;
    if (t < 512) hist[t] = 0;
}

// ---------------- conv1: k=4 s=2 p=1, Cin=3 (scalar, small) ----------------
__global__ void conv_k4s2_kernel(const float* __restrict__ in, const float* __restrict__ w,
                                 const float* __restrict__ bias, float* __restrict__ out,
                                 int Cin, int Hin, int Win, int Cout, int Hout, int Wout,
                                 int outRelu)
{
    __shared__ float s_in[8][34][36];
    __shared__ float s_w[8][8][16];
    int tid = threadIdx.x;
    int ntx = Wout >> 4;
    int tx0 = (blockIdx.x % ntx) << 4, ty0 = (blockIdx.x / ntx) << 4;
    int ocb = blockIdx.y << 3;
    int b = blockIdx.z;
    int px = tid & 15, py = tid >> 4;
    float acc[8];
#pragma unroll
    for (int i = 0; i < 8; i++) acc[i] = 0.f;

    for (int c0 = 0; c0 < Cin; c0 += 8) {
        int cc = min(8, Cin - c0);
        for (int i = tid; i < cc * 34 * 34; i += 256) {
            int ci = i / (34*34); int rr = (i / 34) % 34; int col = i % 34;
            int gy = 2*ty0 - 1 + rr, gx = 2*tx0 - 1 + col;
            float v = 0.f;
            if ((unsigned)gy < (unsigned)Hin && (unsigned)gx < (unsigned)Win)
                v = in[((b*Cin + c0 + ci)*Hin + gy)*Win + gx];
            s_in[ci][rr][col] = v;
        }
        for (int i = tid; i < 8 * cc * 16; i += 256) {
            int oc = i / (cc*16); int ci = (i / 16) % cc; int k = i & 15;
            s_w[oc][ci][k] = w[((ocb+oc)*Cin + c0 + ci)*16 + k];
        }
        __syncthreads();
        for (int ci = 0; ci < cc; ci++) {
            float v[16];
#pragma unroll
            for (int ky = 0; ky < 4; ky++)
#pragma unroll
                for (int kx = 0; kx < 4; kx++)
                    v[ky*4+kx] = s_in[ci][2*py + ky][2*px + kx];
#pragma unroll
            for (int oc = 0; oc < 8; oc++) {
                float a = acc[oc];
#pragma unroll
                for (int k = 0; k < 16; k++) a += v[k] * s_w[oc][ci][k];
                acc[oc] = a;
            }
        }
        __syncthreads();
    }
#pragma unroll
    for (int oc = 0; oc < 8; oc++) {
        float r = acc[oc] + bias[ocb + oc];
        if (outRelu) r = fmaxf(r, 0.f);
        out[((b*Cout + ocb + oc)*Hout + ty0 + py)*Wout + tx0 + px] = r;
    }
}

// ---------------- conv2: k=4 s=2 p=1 packed f32x2 (in 64x64 -> out 32x32) ----------------
__global__ void __launch_bounds__(256, 2)
convk4s2_f2_kernel(const float* __restrict__ in, const float* __restrict__ w,
                   const float* __restrict__ bias, float* __restrict__ out,
                   int Cin, int Cout)
{
    __shared__ float s_in[4][18][68];
    __shared__ ull s_w[4][16][32];
    int tid = threadIdx.x;
    int pos = tid & 31, ocg = tid >> 5;
    int posx = pos & 7, posy = pos >> 3;
    int col0 = posx * 4, row0 = posy * 2;
    int ry0 = blockIdx.x * 8;
    int ocb = blockIdx.y * 64;
    int b = blockIdx.z;
    ull acc[2][4][4];
#pragma unroll
    for (int r = 0; r < 2; r++)
#pragma unroll
        for (int c = 0; c < 4; c++)
#pragma unroll
            for (int j = 0; j < 4; j++) acc[r][c][j] = 0ull;

    float* swf = (float*)s_w;
    for (int c0 = 0; c0 < Cin; c0 += 4) {
        for (int i = tid; i < 4*18*66; i += 256) {
            int ci = i / (18*66); int rr = (i / 66) % 18; int cc = i % 66;
            int gy = 2*ry0 - 1 + rr, gx = cc - 1;
            float v = 0.f;
            if ((unsigned)gy < 64u && (unsigned)gx < 64u)
                v = in[((b*Cin + c0 + ci)*64 + gy)*64 + gx];
            s_in[ci][rr][cc] = v;
        }
        for (int i = tid; i < 64*64; i += 256) {
            int ocl = i >> 6; int t = i & 63; int ci = t >> 4; int k = t & 15;
            swf[(ci*16 + k)*64 + ocl] = w[(ocb + ocl)*Cin*16 + (c0 + ci)*16 + k];
        }
        __syncthreads();
#pragma unroll
        for (int ci = 0; ci < 4; ci++) {
#pragma unroll
            for (int ky = 0; ky < 4; ky++) {
#pragma unroll
                for (int r = 0; r < 2; r++) {
                    int rr = 2*row0 + 2*r + ky;
                    ull vb[10];
#pragma unroll
                    for (int t = 0; t < 10; t++) vb[t] = bc2(s_in[ci][rr][2*col0 + t]);
#pragma unroll
                    for (int kx = 0; kx < 4; kx++) {
                        ull wr[4];
#pragma unroll
                        for (int j = 0; j < 4; j++) wr[j] = s_w[ci][ky*4+kx][ocg*4 + j];
#pragma unroll
                        for (int c = 0; c < 4; c++)
#pragma unroll
                            for (int j = 0; j < 4; j++)
                                ffma2(acc[r][c][j], vb[2*c+kx], wr[j]);
                    }
                }
            }
        }
        __syncthreads();
    }
#pragma unroll
    for (int r = 0; r < 2; r++)
#pragma unroll
        for (int c = 0; c < 4; c++)
#pragma unroll
            for (int j = 0; j < 4; j++) {
                int oc = ocb + ocg*8 + 2*j;
                int row = ry0 + row0 + r, col = col0 + c;
                float v0 = fmaxf(lo32(acc[r][c][j]) + bias[oc], 0.f);
                float v1 = fmaxf(hi32(acc[r][c][j]) + bias[oc+1], 0.f);
                out[((b*Cout + oc)*32 + row)*32 + col] = v0;
                out[((b*Cout + oc+1)*32 + row)*32 + col] = v1;
            }
}

// ---------------- conv 3x3 s=1 p=1 packed f32x2, H=W=32 ----------------
template<int RH, int TOC>
__global__ void __launch_bounds__(256, 2)
conv3x3_f2_kernel(const float* __restrict__ in, const float* __restrict__ w,
                  const float* __restrict__ bias, float* __restrict__ out,
                  int Cin, int Cout, int inRelu)
{
    constexpr int POS = RH * 4;
    constexpr int NCP = TOC / 2;
    __shared__ float s_in[8][RH+2][34];
    __shared__ ull s_w[8][9][16];
    int tid = threadIdx.x;
    int pos = tid % POS, ocg = tid / POS;
    int posx = pos & 7, posy = pos >> 3;
    int col0 = posx * 4, row0 = posy * 2;
    int ry0 = blockIdx.x * RH;
    int ocb = blockIdx.y * 32;
    int b = blockIdx.z;
    ull acc[2][4][NCP];
#pragma unroll
    for (int r = 0; r < 2; r++)
#pragma unroll
        for (int c = 0; c < 4; c++)
#pragma unroll
            for (int j = 0; j < NCP; j++) acc[r][c][j] = 0ull;

    float* swf = (float*)s_w;
    for (int c0 = 0; c0 < Cin; c0 += 8) {
        for (int i = tid; i < 8*(RH+2)*34; i += 256) {
            int ci = i / ((RH+2)*34); int rr = (i / 34) % (RH+2); int cc = i % 34;
            int gy = ry0 - 1 + rr, gx = cc - 1;
            float v = 0.f;
            if ((unsigned)gy < 32u && (unsigned)gx < 32u)
                v = in[((b*Cin + c0 + ci)*32 + gy)*32 + gx];
            if (inRelu) v = fmaxf(v, 0.f);
            s_in[ci][rr][cc] = v;
        }
        for (int i = tid; i < 32*72; i += 256) {
            int ocl = i / 72; int t = i % 72; int ci = t / 9; int k = t % 9;
            swf[(ci*9 + k)*32 + ocl] = w[(ocb + ocl)*Cin*9 + (c0 + ci)*9 + k];
        }
        __syncthreads();
#pragma unroll
        for (int ci = 0; ci < 8; ci++) {
#pragma unroll
            for (int ky = 0; ky < 3; ky++) {
                ull vb0[6], vb1[6];
#pragma unroll
                for (int c = 0; c < 6; c++) {
                    vb0[c] = bc2(s_in[ci][row0 + ky][col0 + c]);
                    vb1[c] = bc2(s_in[ci][row0 + ky + 1][col0 + c]);
                }
#pragma unroll
                for (int kx = 0; kx < 3; kx++) {
                    ull wr[NCP];
#pragma unroll
                    for (int j = 0; j < NCP; j++) wr[j] = s_w[ci][ky*3+kx][ocg*NCP + j];
#pragma unroll
                    for (int c = 0; c < 4; c++)
#pragma unroll
                        for (int j = 0; j < NCP; j++) {
                            ffma2(acc[0][c][j], vb0[c+kx], wr[j]);
                            ffma2(acc[1][c][j], vb1[c+kx], wr[j]);
                        }
                }
            }
        }
        __syncthreads();
    }
#pragma unroll
    for (int r = 0; r < 2; r++)
#pragma unroll
        for (int c = 0; c < 4; c++)
#pragma unroll
            for (int j = 0; j < NCP; j++) {
                int oc = ocb + ocg*TOC + 2*j;
                int row = ry0 + row0 + r, col = col0 + c;
                float b0 = bias ? bias[oc] : 0.f;
                float b1 = bias ? bias[oc+1] : 0.f;
                out[((b*Cout + oc)*32 + row)*32 + col] = lo32(acc[r][c][j]) + b0;
                out[((b*Cout + oc+1)*32 + row)*32 + col] = hi32(acc[r][c][j]) + b1;
            }
}

// ---------------- conv 1x1 packed: relu(in) @ w, +bias, +res ----------------
__global__ void __launch_bounds__(256, 2)
conv1x1_f2_kernel(const float* __restrict__ in, const float* __restrict__ w,
                  const float* __restrict__ bias, const float* __restrict__ hres,
                  float* __restrict__ out, int Cin, int Cout)
{
    __shared__ ull s_w[128][16];
    int tid = threadIdx.x;
    int pos = tid & 63, ocg = tid >> 6;
    int s0 = blockIdx.x * 256 + pos * 4;
    int ocb = blockIdx.y * 32;
    int b = blockIdx.z;
    float* swf = (float*)s_w;
    for (int i = tid; i < Cin * 32; i += 256) {
        int ocl = i / Cin; int ci = i % Cin;
        swf[ci*32 + ocl] = w[(ocb + ocl)*Cin + ci];
    }
    __syncthreads();
    ull acc[4][4];
#pragma unroll
    for (int p = 0; p < 4; p++)
#pragma unroll
        for (int j = 0; j < 4; j++) acc[p][j] = 0ull;

    for (int ci = 0; ci < Cin; ci++) {
        float4 iv = *(const float4*)&in[((size_t)(b*Cin + ci) << 10) + s0];
        ull b0 = bc2(fmaxf(iv.x, 0.f)), b1 = bc2(fmaxf(iv.y, 0.f));
        ull b2 = bc2(fmaxf(iv.z, 0.f)), b3 = bc2(fmaxf(iv.w, 0.f));
        ull wr[4];
#pragma unroll
        for (int j = 0; j < 4; j++) wr[j] = s_w[ci][ocg*4 + j];
#pragma unroll
        for (int j = 0; j < 4; j++) {
            ffma2(acc[0][j], b0, wr[j]);
            ffma2(acc[1][j], b1, wr[j]);
            ffma2(acc[2][j], b2, wr[j]);
            ffma2(acc[3][j], b3, wr[j]);
        }
    }
#pragma unroll
    for (int j = 0; j < 4; j++) {
#pragma unroll
        for (int lane = 0; lane < 2; lane++) {
            int oc = ocb + ocg*8 + 2*j + lane;
            size_t base = (((size_t)b*Cout + oc) << 10) + s0;
            float bv = bias ? bias[oc] : 0.f;
            float4 hv = make_float4(0.f, 0.f, 0.f, 0.f);
            if (hres) hv = *(const float4*)&hres[base];
            float4 ov;
            ov.x = (lane ? hi32(acc[0][j]) : lo32(acc[0][j])) + bv + hv.x;
            ov.y = (lane ? hi32(acc[1][j]) : lo32(acc[1][j])) + bv + hv.y;
            ov.z = (lane ? hi32(acc[2][j]) : lo32(acc[2][j])) + bv + hv.z;
            ov.w = (lane ? hi32(acc[3][j]) : lo32(acc[3][j])) + bv + hv.w;
            *(float4*)&out[base] = ov;
        }
    }
}

// ---------------- vector quantizer (packed dot) ----------------
__global__ void vq_kernel(const float* __restrict__ z, const float* __restrict__ cb,
                          float* __restrict__ qc, int* __restrict__ hist,
                          float* __restrict__ ssep)
{
    __shared__ ull s_cb[128][32];
    __shared__ float s_cn[128];
    __shared__ int s_hist[512];
    __shared__ float s_red[256];
    int tid = threadIdx.x;
    for (int i = tid; i < 512; i += 256) s_hist[i] = 0;

    int n = blockIdx.x * 256 + tid;
    int b = n >> 10, s = n & 1023;
    ull zp[32];
    float zv[64];
#pragma unroll
    for (int d = 0; d < 64; d++) zv[d] = z[(((size_t)b * 64 + d) << 10) + s];
#pragma unroll
    for (int j = 0; j < 32; j++) zp[j] = pack2(zv[2*j], zv[2*j+1]);

    const ull* cbu = (const ull*)cb;
    float best = 3.4e38f; int bi = 0;
    for (int k0 = 0; k0 < 512; k0 += 128) {
        __syncthreads();
        for (int i = tid; i < 128*32; i += 256)
            s_cb[i >> 5][i & 31] = cbu[((size_t)k0 << 5) + i];
        __syncthreads();
        if (tid < 128) {
            float cn = 0.f;
#pragma unroll
            for (int j = 0; j < 32; j++) {
                ull p = s_cb[tid][j];
                float a = lo32(p), bb = hi32(p);
                cn += a*a + bb*bb;
            }
            s_cn[tid] = cn;
        }
        __syncthreads();
        for (int k = 0; k < 128; k++) {
            ull dp = 0ull;
#pragma unroll
            for (int j = 0; j < 32; j++) ffma2(dp, zp[j], s_cb[k][j]);
            float dot = lo32(dp) + hi32(dp);
            float dd = s_cn[k] - 2.f * dot;
            if (dd < best) { best = dd; bi = k0 + k; }
        }
    }
    float sq = 0.f;
    const float* c = cb + ((size_t)bi << 6);
#pragma unroll
    for (int d = 0; d < 64; d++) {
        float cv = c[d];
        qc[(((size_t)b * 64 + d) << 10) + s] = cv;
        float df = cv - zv[d];
        sq += df * df;
    }
    atomicAdd(&s_hist[bi], 1);
    s_red[tid] = sq;
    __syncthreads();
    for (int st = 128; st > 0; st >>= 1) {
        if (tid < st) s_red[tid] += s_red[tid + st];
        __syncthreads();
    }
    if (tid == 0) ssep[blockIdx.x] = s_red[0];
    for (int i = tid; i < 512; i += 256)
        if (s_hist[i]) atomicAdd(&hist[i], s_hist[i]);
}

// ---------------- dt1: convT k=4 s=2 p=1 packed (in 32x32 -> out 64x64) ----------------
// weights oc-major: w[(oc*Cin + ci)*16 + k]  (OIHW, validated in R1)
__global__ void __launch_bounds__(256, 2)
convt_f2_kernel(const float* __restrict__ in, const float* __restrict__ w,
                const float* __restrict__ bias, float* __restrict__ out,
                int Cin, int Cout)
{
    __shared__ float s_in[8][10][20];
    __shared__ ull s_w[8][16][16];
    int tid = threadIdx.x;
    int pos = tid & 31, ocg = tid >> 5;
    int posx = pos & 3, posy = pos >> 2;
    int col0 = posx * 8, row0 = posy * 2;
    int tx = blockIdx.x & 1, ty = blockIdx.x >> 1;
    int cx0 = tx * 32, ry0 = ty * 16;
    int ocb = blockIdx.y * 32;
    int b = blockIdx.z;
    ull acc[2][8][2];
#pragma unroll
    for (int r = 0; r < 2; r++)
#pragma unroll
        for (int c = 0; c < 8; c++)
#pragma unroll
            for (int j = 0; j < 2; j++) acc[r][c][j] = 0ull;

    float* swf = (float*)s_w;
    for (int c0 = 0; c0 < Cin; c0 += 8) {
        for (int i = tid; i < 8*10*18; i += 256) {
            int ci = i / 180; int rr = (i / 18) % 10; int cc = i % 18;
            int gy = (ry0 >> 1) - 1 + rr, gx = (cx0 >> 1) - 1 + cc;
            float v = 0.f;
            if ((unsigned)gy < 32u && (unsigned)gx < 32u)
                v = fmaxf(in[((b*Cin + c0 + ci)*32 + gy)*32 + gx], 0.f);
            s_in[ci][rr][cc] = v;
        }
        for (int i = tid; i < 32*128; i += 256) {
            int ocl = i >> 7; int t = i & 127; int ci = t >> 4; int k = t & 15;
            swf[(ci*16 + k)*32 + ocl] = w[((size_t)(ocb + ocl)*Cin + c0 + ci)*16 + k];
        }
        __syncthreads();
#pragma unroll
        for (int ci = 0; ci < 8; ci++) {
            ull vb[3][6];
#pragma unroll
            for (int rr = 0; rr < 3; rr++)
#pragma unroll
                for (int cc = 0; cc < 6; cc++)
                    vb[rr][cc] = bc2(s_in[ci][posy + rr][posx*4 + cc]);
#pragma unroll
            for (int r = 0; r < 2; r++) {
#pragma unroll
                for (int kxp = 0; kxp < 2; kxp++) {
                    ull wr[4][2];
                    int t0 = r*4 + kxp, t2 = (r+2)*4 + kxp;
#pragma unroll
                    for (int j = 0; j < 2; j++) {
                        wr[0][j] = s_w[ci][t0][ocg*2 + j];
                        wr[1][j] = s_w[ci][t0+2][ocg*2 + j];
                        wr[2][j] = s_w[ci][t2][ocg*2 + j];
                        wr[3][j] = s_w[ci][t2+2][ocg*2 + j];
                    }
#pragma unroll
                    for (int cs = 0; cs < 4; cs++) {
                        int c = 2*cs + kxp;
                        int cq = cs + kxp;
#pragma unroll
                        for (int j = 0; j < 2; j++) {
                            ffma2(acc[r][c][j], vb[r][cq],     wr[0][j]);
                            ffma2(acc[r][c][j], vb[r][cq+1],   wr[1][j]);
                            ffma2(acc[r][c][j], vb[r+1][cq],   wr[2][j]);
                            ffma2(acc[r][c][j], vb[r+1][cq+1], wr[3][j]);
                        }
                    }
                }
            }
        }
        __syncthreads();
    }
#pragma unroll
    for (int r = 0; r < 2; r++)
#pragma unroll
        for (int c = 0; c < 8; c++)
#pragma unroll
            for (int j = 0; j < 2; j++) {
                int oc = ocb + ocg*4 + 2*j;
                int oy = ry0 + row0 + r, ox = cx0 + col0 + c;
                float v0 = fmaxf(lo32(acc[r][c][j]) + bias[oc], 0.f);
                float v1 = fmaxf(hi32(acc[r][c][j]) + bias[oc+1], 0.f);
                out[(((size_t)b*Cout + oc)*64 + oy)*64 + ox] = v0;
                out[(((size_t)b*Cout + oc+1)*64 + oy)*64 + ox] = v1;
            }
}

// ---------------- dt2: convT k=4 s=2 p=1 scalar (64->3, out 128x128) ----------------
// weights oc-major (OIHW), as validated in R1
__global__ void convt4s2_kernel(const float* __restrict__ in, const float* __restrict__ w,
                                const float* __restrict__ bias, float* __restrict__ out,
                                int Cin, int Hin, int Win, int Cout, int inRelu, int outRelu)
{
    __shared__ float s_in[8][10][12];
    __shared__ float s_w[8][8][16];
    int tid = threadIdx.x;
    int Hout = Hin * 2, Wout = Win * 2;
    int ntx = Wout >> 4;
    int ox0 = (blockIdx.x % ntx) << 4, oy0 = (blockIdx.x / ntx) << 4;
    int ocb = blockIdx.y << 3;
    int b = blockIdx.z;
    int px = tid & 15, py = tid >> 4;
    int iy0 = oy0 >> 1, ix0 = ox0 >> 1;
    float acc[8];
#pragma unroll
    for (int i = 0; i < 8; i++) acc[i] = 0.f;

    for (int c0 = 0; c0 < Cin; c0 += 8) {
        for (int i = tid; i < 8 * 10 * 10; i += 256) {
            int ci = i / 100; int rr = (i / 10) % 10; int col = i % 10;
            int gy = iy0 - 1 + rr, gx = ix0 - 1 + col;
            float v = 0.f;
            if ((unsigned)gy < (unsigned)Hin && (unsigned)gx < (unsigned)Win)
                v = in[((b*Cin + c0 + ci)*Hin + gy)*Win + gx];
            if (inRelu) v = fmaxf(v, 0.f);
            s_in[ci][rr][col] = v;
        }
        for (int i = tid; i < 8 * 8 * 16; i += 256) {
            int oc = i >> 7; int ci = (i >> 4) & 7; int k = i & 15;
            int oco = ocb + oc;
            s_w[oc][ci][k] = (oco < Cout) ? w[((size_t)oco * Cin + c0 + ci)*16 + k] : 0.f;
        }
        __syncthreads();
        int ky0 = py & 1, kx0 = px & 1;
        int r0 = (py + ky0) >> 1;
        int q0 = (px + kx0) >> 1;
#pragma unroll
        for (int ci = 0; ci < 8; ci++) {
            float v00 = s_in[ci][r0][q0];
            float v01 = s_in[ci][r0][q0 + 1];
            float v10 = s_in[ci][r0 + 1][q0];
            float v11 = s_in[ci][r0 + 1][q0 + 1];
#pragma unroll
            for (int oc = 0; oc < 8; oc++) {
                float a = acc[oc];
                a += v00 * s_w[oc][ci][ky0*4 + kx0];
                a += v01 * s_w[oc][ci][ky0*4 + kx0 + 2];
                a += v10 * s_w[oc][ci][(ky0+2)*4 + kx0];
                a += v11 * s_w[oc][ci][(ky0+2)*4 + kx0 + 2];
                acc[oc] = a;
            }
        }
        __syncthreads();
    }
#pragma unroll
    for (int oc = 0; oc < 8; oc++) {
        int oco = ocb + oc;
        if (oco < Cout) {
            float r = acc[oc] + bias[oco];
            if (outRelu) r = fmaxf(r, 0.f);
            out[(((size_t)b * Cout + oco)*Hout + oy0 + py)*Wout + ox0 + px] = r;
        }
    }
}

// ---------------- finalize ----------------
__global__ void finalize_kernel(const int* __restrict__ hist, const float* __restrict__ ssep,
                                float* __restrict__ out, int lastIdx)
{
    __shared__ float red[512];
    __shared__ float red2[128];
    int t = threadIdx.x;
    float p = hist[t] * (1.0f / 32768.0f);
    red[t] = p * logf(p + 1e-10f);
    if (t < 128) red2[t] = ssep[t];
    __syncthreads();
    for (int st = 256; st > 0; st >>= 1) {
        if (t < st) red[t] += red[t + st];
        __syncthreads();
    }
    for (int st = 64; st > 0; st >>= 1) {
        if (t < st) red2[t] += red2[t + st];
        __syncthreads();
    }
    if (t == 0) {
        out[0] = red2[0] * 1.25f / (32768.0f * 64.0f);
        out[lastIdx] = expf(-red[0]);
    }
}

// ---------------- launch ----------------
extern "C" void kernel_launch(void* const* d_in, const int* in_sizes, int n_in,
                              void* d_out, int out_size)
{
    const float* x     = (const float*)d_in[0];
    const float* e_w1  = (const float*)d_in[1];
    const float* e_b1  = (const float*)d_in[2];
    const float* e_w2  = (const float*)d_in[3];
    const float* e_b2  = (const float*)d_in[4];
    const float* e_w3  = (const float*)d_in[5];
    const float* e_b3  = (const float*)d_in[6];
    const float* e_r1a = (const float*)d_in[7];
    const float* e_r1b = (const float*)d_in[8];
    const float* e_r2a = (const float*)d_in[9];
    const float* e_r2b = (const float*)d_in[10];
    const float* pre_w = (const float*)d_in[11];
    const float* pre_b = (const float*)d_in[12];
    const float* cb    = (const float*)d_in[13];
    const float* d_w1  = (const float*)d_in[14];
    const float* d_b1  = (const float*)d_in[15];
    const float* d_r1a = (const float*)d_in[16];
    const float* d_r1b = (const float*)d_in[17];
    const float* d_r2a = (const float*)d_in[18];
    const float* d_r2b = (const float*)d_in[19];
    const float* dt_w1 = (const float*)d_in[20];
    const float* dt_b1 = (const float*)d_in[21];
    const float* dt_w2 = (const float*)d_in[22];
    const float* dt_b2 = (const float*)d_in[23];
    float* out = (float*)d_out;

    float *A, *Bb, *C, *R, *Z, *Q, *ssep; int* hist;
    cudaGetSymbolAddress((void**)&A,    g_A);
    cudaGetSymbolAddress((void**)&Bb,   g_B);
    cudaGetSymbolAddress((void**)&C,    g_C);
    cudaGetSymbolAddress((void**)&R,    g_R);
    cudaGetSymbolAddress((void**)&Z,    g_Z);
    cudaGetSymbolAddress((void**)&Q,    g_Q);
    cudaGetSymbolAddress((void**)&ssep, g_ssep);
    cudaGetSymbolAddress((void**)&hist, g_hist);

    zero_kernel<<<2, 256>>>(hist);

    // ---- encoder ----
    conv_k4s2_kernel<<<dim3(16, 8, BATCH), 256>>>(x, e_w1, e_b1, A, 3, 128, 128, 64, 64, 64, 1);
    convk4s2_f2_kernel<<<dim3(4, 2, BATCH), 256>>>(A, e_w2, e_b2, Bb, 64, 128);
    conv3x3_f2_kernel<16, 8><<<dim3(2, 4, BATCH), 256>>>(Bb, e_w3, e_b3, C, 128, 128, 0);
    conv3x3_f2_kernel<8, 4><<<dim3(4, 1, BATCH), 256>>>(C, e_r1a, nullptr, R, 128, 32, 1);
    conv1x1_f2_kernel<<<dim3(4, 4, BATCH), 256>>>(R, e_r1b, nullptr, C, C, 32, 128);
    conv3x3_f2_kernel<8, 4><<<dim3(4, 1, BATCH), 256>>>(C, e_r2a, nullptr, R, 128, 32, 1);
    conv1x1_f2_kernel<<<dim3(4, 4, BATCH), 256>>>(R, e_r2b, nullptr, C, C, 32, 128);
    conv1x1_f2_kernel<<<dim3(4, 2, BATCH), 256>>>(C, pre_w, pre_b, nullptr, Z, 128, 64);

    // ---- VQ ----
    vq_kernel<<<128, 256>>>(Z, cb, Q, hist, ssep);

    // ---- decoder ----
    conv3x3_f2_kernel<16, 8><<<dim3(2, 4, BATCH), 256>>>(Q, d_w1, d_b1, Bb, 64, 128, 0);
    conv3x3_f2_kernel<8, 4><<<dim3(4, 1, BATCH), 256>>>(Bb, d_r1a, nullptr, R, 128, 32, 1);
    conv1x1_f2_kernel<<<dim3(4, 4, BATCH), 256>>>(R, d_r1b, nullptr, Bb, Bb, 32, 128);
    conv3x3_f2_kernel<8, 4><<<dim3(4, 1, BATCH), 256>>>(Bb, d_r2a, nullptr, R, 128, 32, 1);
    conv1x1_f2_kernel<<<dim3(4, 4, BATCH), 256>>>(R, d_r2b, nullptr, Bb, Bb, 32, 128);
    convt_f2_kernel<<<dim3(8, 2, BATCH), 256>>>(Bb, dt_w1, dt_b1, A, 128, 64);
    convt4s2_kernel<<<dim3(64, 1, BATCH), 256>>>(A, dt_w2, dt_b2, out + 1, 64, 64, 64, 3, 0, 0);

    finalize_kernel<<<1, 512>>>(hist, ssep, out, out_size - 1);
}